// round 2
// baseline (speedup 1.0000x reference)
#include <cuda_runtime.h>
#include <math.h>

__device__ static constexpr float CT16[16] = {
     1.f, 0.9238795325112867f, 0.7071067811865476f, 0.3826834323650898f,
     0.f,-0.3826834323650898f,-0.7071067811865476f,-0.9238795325112867f,
    -1.f,-0.9238795325112867f,-0.7071067811865476f,-0.3826834323650898f,
     0.f, 0.3826834323650898f, 0.7071067811865476f, 0.9238795325112867f };
__device__ static constexpr float ST16[16] = {
     0.f, 0.3826834323650898f, 0.7071067811865476f, 0.9238795325112867f,
     1.f, 0.9238795325112867f, 0.7071067811865476f, 0.3826834323650898f,
     0.f,-0.3826834323650898f,-0.7071067811865476f,-0.9238795325112867f,
    -1.f,-0.9238795325112867f,-0.7071067811865476f,-0.3826834323650898f };

// in-place radix-2 DIT, N=8 or 16. sgn=-1 fwd, +1 inv (unnormalized).
template<int N>
__device__ __forceinline__ void fftN(float* re, float* im, const float sgn) {
#define SWP(a,b) { float t_=re[a]; re[a]=re[b]; re[b]=t_; t_=im[a]; im[a]=im[b]; im[b]=t_; }
    if constexpr (N == 16) { SWP(1,8) SWP(2,4) SWP(3,12) SWP(5,10) SWP(7,14) SWP(11,13) }
    else                   { SWP(1,4) SWP(3,6) }
#undef SWP
#pragma unroll
    for (int len = 2; len <= N; len <<= 1) {
#pragma unroll
        for (int j = 0; j < len/2; j++) {
            const float c = CT16[j*(16/len)];
            const float s = sgn*ST16[j*(16/len)];
#pragma unroll
            for (int i = j; i < N; i += len) {
                const int hi = i + len/2;
                const float tr = c*re[hi] - s*im[hi];
                const float ti = c*im[hi] + s*re[hi];
                re[hi] = re[i] - tr; im[hi] = im[i] - ti;
                re[i] += tr;         im[i] += ti;
            }
        }
    }
}

__device__ __forceinline__ void ln8(const float* v, const float* g, const float* b, float* o) {
    float m = 0.f;
#pragma unroll
    for (int c = 0; c < 8; c++) m += v[c];
    m *= 0.125f;
    float var = 0.f;
#pragma unroll
    for (int c = 0; c < 8; c++) { float d = v[c]-m; var += d*d; }
    const float r = rsqrtf(var*0.125f + 1e-5f);
#pragma unroll
    for (int c = 0; c < 8; c++) o[c] = (v[c]-m)*r*g[c] + b[c];
}

// WS layout (floats):
// 0 n1g 8 n1b 16 n2g 24 n2b 32 n3g 40 n3b 48 n4g 56 n4b
// 64 conv1T[576] 640 conv1b  648 conv2T[576] 1224 conv2b
// 1232 m1w1[256] 1488 m1b1[32] 1520 m1w2[256] 1776 m1b2[8]
// 1784 m2w1[256] 2040 m2b1[32] 2072 m2w2[256] 2328 m2b2[8]  -> 2336
#define T1_OFF   2336
#define T2_OFF   4640
#define SCR_OFF  6944
#define SMEM_FLOATS 11296   // 45184 B

template<int H>
__device__ void run_branch(const float* __restrict__ gtok, float* __restrict__ gout,
                           const float* __restrict__ spec, const float* __restrict__ WS,
                           float* __restrict__ t1, float* __restrict__ t2, float* __restrict__ scr,
                           int oCW, int oCB, int oW1, int oB1, int oW2, int oB2, int oNog)
{
    constexpr int N  = H*H;
    constexpr int HH = H/2 + 1;
    const int tid  = threadIdx.x;
    const int lane = tid & 31;
    const int wid  = tid >> 5;

    // raw tokens -> scr (contiguous [t][c])
    for (int i = tid; i < N*2; i += 256)
        reinterpret_cast<float4*>(scr)[i] = reinterpret_cast<const float4*>(gtok)[i];
    __syncthreads();

    // LN1 -> t1 (stride-9 rows)
    if (tid < N) {
        float v[8], o[8];
#pragma unroll
        for (int c = 0; c < 8; c++) v[c] = scr[tid*8+c];
        ln8(v, WS+0, WS+8, o);
#pragma unroll
        for (int c = 0; c < 8; c++) t1[tid*9+c] = o[c];
    }
    __syncthreads();

    // spectral filter: one warp per channel
    {
        const int c = wid;
        float* sre = scr + c*544;   // [16][17] padded
        float* sim = sre + 272;
        float re[H], im[H];

        // FFT over w for each h=lane; store [kw][h]
        if (lane < H) {
#pragma unroll
            for (int j = 0; j < H; j++) { re[j] = t1[(lane*H+j)*9 + c]; im[j] = 0.f; }
            fftN<H>(re, im, -1.f);
#pragma unroll
            for (int kw = 0; kw < H; kw++) { sre[kw*17+lane] = re[kw]; sim[kw*17+lane] = im[kw]; }
        }
        __syncwarp();
        // FFT over h for each kw=lane; * weight; store [kh][kw]
        if (lane < H) {
#pragma unroll
            for (int j = 0; j < H; j++) { re[j] = sre[lane*17+j]; im[j] = sim[lane*17+j]; }
        }
        __syncwarp();
        if (lane < H) {
            fftN<H>(re, im, -1.f);
#pragma unroll
            for (int kh = 0; kh < HH; kh++) {
                const float wr = spec[((lane*HH+kh)*8 + c)*2 + 0];
                const float wi = spec[((lane*HH+kh)*8 + c)*2 + 1];
                sre[kh*17+lane] = re[kh]*wr - im[kh]*wi;
                sim[kh*17+lane] = re[kh]*wi + im[kh]*wr;
            }
        }
        __syncwarp();
        // inverse FFT over kw for each kh=lane; store [w][kh]
        if (lane < HH) {
#pragma unroll
            for (int j = 0; j < H; j++) { re[j] = sre[lane*17+j]; im[j] = sim[lane*17+j]; }
        }
        __syncwarp();
        if (lane < HH) {
            fftN<H>(re, im, 1.f);
#pragma unroll
            for (int w = 0; w < H; w++) { sre[w*17+lane] = re[w]; sim[w*17+lane] = im[w]; }
        }
        __syncwarp();
        // irfft over kh for each w=lane (drop imag of DC/Nyquist); scale 1/N
        if (lane < H) {
            float br[HH], bi[HH];
#pragma unroll
            for (int k = 0; k < HH; k++) { br[k] = sre[lane*17+k]; bi[k] = sim[lane*17+k]; }
#pragma unroll
            for (int h = 0; h < H; h++) {
                float y = br[0] + ((h & 1) ? -br[HH-1] : br[HH-1]);
#pragma unroll
                for (int k = 1; k < H/2; k++) {
                    const int idx = (k*h*(16/H)) & 15;
                    y += 2.f*(br[k]*CT16[idx] - bi[k]*ST16[idx]);
                }
                t2[(h*H+lane)*9 + c] = y*(1.f/(float)N);
            }
        }
    }
    __syncthreads();

    // fused LN2 + MLP + conv3x3(t1) + LN3 + relu
    if (tid < N) {
        float v[8], xn[8];
#pragma unroll
        for (int c = 0; c < 8; c++) v[c] = t2[tid*9+c];
        ln8(v, WS+16, WS+24, xn);

        float hb[32];
        {
            const float* b1 = WS + oB1;
#pragma unroll
            for (int j = 0; j < 32; j++) hb[j] = b1[j];
#pragma unroll
            for (int c = 0; c < 8; c++) {
                const float xc = xn[c];
                const float4* wr = reinterpret_cast<const float4*>(WS + oW1 + c*32);
#pragma unroll
                for (int q = 0; q < 8; q++) {
                    const float4 w = wr[q];
                    hb[q*4+0] += xc*w.x; hb[q*4+1] += xc*w.y;
                    hb[q*4+2] += xc*w.z; hb[q*4+3] += xc*w.w;
                }
            }
#pragma unroll
            for (int j = 0; j < 32; j++) {
                const float u = hb[j];
                hb[j] = 0.5f*u*(1.f + erff(u*0.7071067811865476f));
            }
        }

        float acc[8];
        {
            const float* b2 = WS + oB2;
            const float* cb = WS + oCB;
#pragma unroll
            for (int c = 0; c < 8; c++) acc[c] = b2[c] + cb[c];
#pragma unroll
            for (int j = 0; j < 32; j++) {
                const float hj = hb[j];
                const float4* wr = reinterpret_cast<const float4*>(WS + oW2 + j*8);
                const float4 w0 = wr[0], w1 = wr[1];
                acc[0] += hj*w0.x; acc[1] += hj*w0.y; acc[2] += hj*w0.z; acc[3] += hj*w0.w;
                acc[4] += hj*w1.x; acc[5] += hj*w1.y; acc[6] += hj*w1.z; acc[7] += hj*w1.w;
            }
        }

        // conv3x3 on t1, weights [tap][ci][co]
        {
            const int hh = tid / H, ww = tid % H;
#pragma unroll
            for (int dy = 0; dy < 3; dy++) {
                const int yy = hh + dy - 1;
                if (yy < 0 || yy >= H) continue;
#pragma unroll
                for (int dx = 0; dx < 3; dx++) {
                    const int xx = ww + dx - 1;
                    if (xx < 0 || xx >= H) continue;
                    const float* tin = t1 + (yy*H+xx)*9;
                    const float4* wb = reinterpret_cast<const float4*>(WS + oCW + (dy*3+dx)*64);
#pragma unroll
                    for (int ci = 0; ci < 8; ci++) {
                        const float vin = tin[ci];
                        const float4 w0 = wb[ci*2], w1 = wb[ci*2+1];
                        acc[0] += vin*w0.x; acc[1] += vin*w0.y; acc[2] += vin*w0.z; acc[3] += vin*w0.w;
                        acc[4] += vin*w1.x; acc[5] += vin*w1.y; acc[6] += vin*w1.z; acc[7] += vin*w1.w;
                    }
                }
            }
        }

        float o[8];
        ln8(acc, WS+oNog, WS+oNog+8, o);
        float4* gp = reinterpret_cast<float4*>(gout + tid*8);
        gp[0] = make_float4(fmaxf(o[0],0.f), fmaxf(o[1],0.f), fmaxf(o[2],0.f), fmaxf(o[3],0.f));
        gp[1] = make_float4(fmaxf(o[4],0.f), fmaxf(o[5],0.f), fmaxf(o[6],0.f), fmaxf(o[7],0.f));
    }
    __syncthreads();
}

__global__ void __launch_bounds__(256)
sg_kernel(const float* __restrict__ x,
          const float* __restrict__ n1g, const float* __restrict__ n1b,
          const float* __restrict__ n2g, const float* __restrict__ n2b,
          const float* __restrict__ n3g, const float* __restrict__ n3b,
          const float* __restrict__ n4g, const float* __restrict__ n4b,
          const float* __restrict__ c1w, const float* __restrict__ c1b,
          const float* __restrict__ c2w, const float* __restrict__ c2b,
          const float* __restrict__ m1w1, const float* __restrict__ m1b1,
          const float* __restrict__ m1w2, const float* __restrict__ m1b2,
          const float* __restrict__ m2w1, const float* __restrict__ m2b1,
          const float* __restrict__ m2w2, const float* __restrict__ m2b2,
          const float* __restrict__ cw,  const float* __restrict__ cwz,
          float* __restrict__ out, int nb)
{
    __shared__ float smem[SMEM_FLOATS];
    float* WS  = smem;
    float* t1  = smem + T1_OFF;
    float* t2  = smem + T2_OFF;
    float* scr = smem + SCR_OFF;
    const int tid = threadIdx.x;

    // stage weights once per CTA
    if (tid < 8) {
        WS[tid]      = n1g[tid]; WS[8+tid]    = n1b[tid];
        WS[16+tid]   = n2g[tid]; WS[24+tid]   = n2b[tid];
        WS[32+tid]   = n3g[tid]; WS[40+tid]   = n3b[tid];
        WS[48+tid]   = n4g[tid]; WS[56+tid]   = n4b[tid];
        WS[640+tid]  = c1b[tid]; WS[1224+tid] = c2b[tid];
        WS[1776+tid] = m1b2[tid];WS[2328+tid] = m2b2[tid];
    }
    if (tid < 32) { WS[1488+tid] = m1b1[tid]; WS[2040+tid] = m2b1[tid]; }
    {
        const int i = tid;                        // 256 threads, 256 elems
        WS[1232+i] = m1w1[i]; WS[1520+i] = m1w2[i];
        WS[1784+i] = m2w1[i]; WS[2072+i] = m2w2[i];
    }
    for (int i = tid; i < 576; i += 256) {        // conv OIHW -> [tap][ci][co]
        const int co = i/72, r = i%72, ci = r/9, tap = r%9;
        WS[64  + tap*64 + ci*8 + co] = c1w[i];
        WS[648 + tap*64 + ci*8 + co] = c2w[i];
    }
    __syncthreads();

    for (int b = blockIdx.x; b < nb; b += gridDim.x) {
        const float* xb = x   + (size_t)b*2560;
        float*       ob = out + (size_t)b*2560;
        // x-branch: tokens 64..319, H=16
        run_branch<16>(xb+512, ob+512, cw,  WS, t1, t2, scr,
                       64, 640, 1232, 1488, 1520, 1776, 32);
        // z-branch: tokens 0..63, H=8
        run_branch<8>(xb, ob, cwz, WS, t1, t2, scr,
                      648, 1224, 1784, 2040, 2072, 2328, 48);
    }
}

extern "C" void kernel_launch(void* const* d_in, const int* in_sizes, int n_in,
                              void* d_out, int out_size) {
    const float* P[23];
    for (int i = 0; i < 23; i++) P[i] = (const float*)d_in[i];
    const int nb = in_sizes[0] / 2560;
    sg_kernel<<<1184, 256>>>(P[0], P[1], P[2], P[3], P[4], P[5], P[6], P[7], P[8],
                             P[9], P[10], P[11], P[12], P[13], P[14], P[15], P[16],
                             P[17], P[18], P[19], P[20], P[21], P[22],
                             (float*)d_out, nb);
}

// round 3
// speedup vs baseline: 1.6712x; 1.6712x over previous
#include <cuda_runtime.h>
#include <math.h>

// ---------------- twiddles ----------------
__device__ static constexpr float CT16[16] = {
     1.f, 0.9238795325112867f, 0.7071067811865476f, 0.3826834323650898f,
     0.f,-0.3826834323650898f,-0.7071067811865476f,-0.9238795325112867f,
    -1.f,-0.9238795325112867f,-0.7071067811865476f,-0.3826834323650898f,
     0.f, 0.3826834323650898f, 0.7071067811865476f, 0.9238795325112867f };
__device__ static constexpr float ST16[16] = {
     0.f, 0.3826834323650898f, 0.7071067811865476f, 0.9238795325112867f,
     1.f, 0.9238795325112867f, 0.7071067811865476f, 0.3826834323650898f,
     0.f,-0.3826834323650898f,-0.7071067811865476f,-0.9238795325112867f,
    -1.f,-0.9238795325112867f,-0.7071067811865476f,-0.3826834323650898f };

template<int N>
__device__ __forceinline__ void fftN(float* re, float* im, const float sgn) {
#define SWP(a,b) { float t_=re[a]; re[a]=re[b]; re[b]=t_; t_=im[a]; im[a]=im[b]; im[b]=t_; }
    if constexpr (N == 16) { SWP(1,8) SWP(2,4) SWP(3,12) SWP(5,10) SWP(7,14) SWP(11,13) }
    else                   { SWP(1,4) SWP(3,6) }
#undef SWP
#pragma unroll
    for (int len = 2; len <= N; len <<= 1) {
#pragma unroll
        for (int j = 0; j < len/2; j++) {
            const float c = CT16[j*(16/len)];
            const float s = sgn*ST16[j*(16/len)];
#pragma unroll
            for (int i = j; i < N; i += len) {
                const int hi = i + len/2;
                const float tr = c*re[hi] - s*im[hi];
                const float ti = c*im[hi] + s*re[hi];
                re[hi] = re[i] - tr; im[hi] = im[i] - ti;
                re[i] += tr;         im[i] += ti;
            }
        }
    }
}

__device__ __forceinline__ void ln8(const float* v, const float* g, const float* b, float* o) {
    float m = 0.f;
#pragma unroll
    for (int c = 0; c < 8; c++) m += v[c];
    m *= 0.125f;
    float var = 0.f;
#pragma unroll
    for (int c = 0; c < 8; c++) { float d = v[c]-m; var += d*d; }
    const float r = rsqrtf(var*0.125f + 1e-5f);
#pragma unroll
    for (int c = 0; c < 8; c++) o[c] = (v[c]-m)*r*g[c] + b[c];
}

// ---------------- smem layout (floats) ----------------
// WS:
//  0 n1g  8 n1b  16 n2g 24 n2b 32 n3g 40 n3b 48 n4g 56 n4b
//  64 c1T[576] 640 c1b[8]   648 c2T[576] 1224 c2b[8]
//  1232 m1w1t[32*12] 1616 m1w2[256] 1872 m1b2[8]
//  1880 m2w1t[32*12] 2264 m2w2[256] 2520 m2b2[8]  -> 2528
#define OFF_T1   2528      // 256 tokens * stride 12 = 3072
#define OFF_CB   5600      // conv buffer 256*8 = 2048
#define OFF_PL   7648      // planes 4608
#define SMEM_FLOATS 12256  // 49024 B

// x planes: re: PL + c*272 ([16][17]); im: PL + 2176 + c*272
// z planes: re: PL + P*72  ([8][9]);   im: PL + 2304 + P*72   (P = sb*8+c)

// conv: accumulate 8 outputs for token (h,w) of one image in t1 (stride 12)
template<int H>
__device__ __forceinline__ void conv_acc(float* acc, const float* t1img, int h, int w,
                                         const float* wsCW) {
#pragma unroll
    for (int dy = 0; dy < 3; dy++) {
        const int yy = h + dy - 1;
        if ((unsigned)yy >= (unsigned)H) continue;
#pragma unroll
        for (int dx = 0; dx < 3; dx++) {
            const int xx = w + dx - 1;
            if ((unsigned)xx >= (unsigned)H) continue;
            const float* tin = t1img + (yy*H+xx)*12;
            const float4 i0 = *reinterpret_cast<const float4*>(tin);
            const float4 i1 = *reinterpret_cast<const float4*>(tin+4);
            const float vin[8] = {i0.x,i0.y,i0.z,i0.w,i1.x,i1.y,i1.z,i1.w};
            const float* wt = wsCW + (dy*3+dx)*64;
#pragma unroll
            for (int ci = 0; ci < 8; ci++) {
                const float4 w0 = *reinterpret_cast<const float4*>(wt + ci*8);
                const float4 w1 = *reinterpret_cast<const float4*>(wt + ci*8 + 4);
                const float vv = vin[ci];
                acc[0] += vv*w0.x; acc[1] += vv*w0.y; acc[2] += vv*w0.z; acc[3] += vv*w0.w;
                acc[4] += vv*w1.x; acc[5] += vv*w1.y; acc[6] += vv*w1.z; acc[7] += vv*w1.w;
            }
        }
    }
}

// MLP j-loop (8->32 gelu ->8 accumulated into acc) + LN + relu + store
__device__ __forceinline__ void mlp_ln_store(const float* xn, float* acc, const float* WS,
                                             int oW1T, int oW2, const float* gm, const float* gb,
                                             float* gout_tok, bool act) {
#pragma unroll 8
    for (int j = 0; j < 32; j++) {
        const float4 wa = *reinterpret_cast<const float4*>(WS + oW1T + j*12);
        const float4 wb = *reinterpret_cast<const float4*>(WS + oW1T + j*12 + 4);
        float hj = WS[oW1T + j*12 + 8];
        hj += xn[0]*wa.x + xn[1]*wa.y + xn[2]*wa.z + xn[3]*wa.w
            + xn[4]*wb.x + xn[5]*wb.y + xn[6]*wb.z + xn[7]*wb.w;
        const float g = 0.5f*hj*(1.f + erff(hj*0.7071067811865476f));
        const float4 va = *reinterpret_cast<const float4*>(WS + oW2 + j*8);
        const float4 vb = *reinterpret_cast<const float4*>(WS + oW2 + j*8 + 4);
        acc[0] += g*va.x; acc[1] += g*va.y; acc[2] += g*va.z; acc[3] += g*va.w;
        acc[4] += g*vb.x; acc[5] += g*vb.y; acc[6] += g*vb.z; acc[7] += g*vb.w;
    }
    float o[8];
    ln8(acc, gm, gb, o);
    if (act) {
        float4* gp = reinterpret_cast<float4*>(gout_tok);
        gp[0] = make_float4(fmaxf(o[0],0.f), fmaxf(o[1],0.f), fmaxf(o[2],0.f), fmaxf(o[3],0.f));
        gp[1] = make_float4(fmaxf(o[4],0.f), fmaxf(o[5],0.f), fmaxf(o[6],0.f), fmaxf(o[7],0.f));
    }
}

// ---------------- x branch: single batch, H=16 ----------------
__device__ void branch_x(const float* __restrict__ gtok, float* __restrict__ gout,
                         const float* __restrict__ spec, float* __restrict__ smem, bool act) {
    float* WS = smem;
    float* t1 = smem + OFF_T1;
    float* cb = smem + OFF_CB;
    float* PL = smem + OFF_PL;
    const int tid = threadIdx.x;
    const int lane = tid & 31;
    const int wid  = tid >> 5;

    // LN1 -> t1 (stride 12) + FFT input planes (im-plane, layout [w][h])
    {
        const int t = tid;
        float v[8] = {0,0,0,0,0,0,0,0};
        if (act) {
            const float4 a = *reinterpret_cast<const float4*>(gtok + t*8);
            const float4 b = *reinterpret_cast<const float4*>(gtok + t*8 + 4);
            v[0]=a.x; v[1]=a.y; v[2]=a.z; v[3]=a.w; v[4]=b.x; v[5]=b.y; v[6]=b.z; v[7]=b.w;
        }
        float o[8];
        ln8(v, WS+0, WS+8, o);
        *reinterpret_cast<float4*>(t1 + t*12)     = make_float4(o[0],o[1],o[2],o[3]);
        *reinterpret_cast<float4*>(t1 + t*12 + 4) = make_float4(o[4],o[5],o[6],o[7]);
        const int h = t >> 4, w = t & 15;
#pragma unroll
        for (int c = 0; c < 8; c++) PL[2176 + c*272 + w*17 + h] = o[c];
    }
    __syncthreads();

    if (wid < 4) {
        // spectral filter: 2 channels per warp, 16 lanes each
        const int c = wid*2 + (lane >> 4);
        const int l = lane & 15;
        float* pre = PL + c*272;
        float* pim = PL + 2176 + c*272;
        float re[16], im[16];
        // stage1: FFT over w for row h=l (input in pim [w][h]); write [kw][h] (own column)
#pragma unroll
        for (int j = 0; j < 16; j++) { re[j] = pim[j*17 + l]; im[j] = 0.f; }
        fftN<16>(re, im, -1.f);
#pragma unroll
        for (int k = 0; k < 16; k++) { pre[k*17 + l] = re[k]; pim[k*17 + l] = im[k]; }
        __syncwarp();
        // stage2: FFT over h for kw=l; * spectral weight; write [kh][kw]
#pragma unroll
        for (int j = 0; j < 16; j++) { re[j] = pre[l*17 + j]; im[j] = pim[l*17 + j]; }
        __syncwarp();
        fftN<16>(re, im, -1.f);
#pragma unroll
        for (int kh = 0; kh < 9; kh++) {
            const float wr = __ldg(&spec[((l*9 + kh)*8 + c)*2 + 0]);
            const float wi = __ldg(&spec[((l*9 + kh)*8 + c)*2 + 1]);
            pre[kh*17 + l] = re[kh]*wr - im[kh]*wi;
            pim[kh*17 + l] = re[kh]*wi + im[kh]*wr;
        }
        __syncwarp();
        // stage3: inverse FFT over kw for kh=l (l<9); write [w][kh]
        if (l < 9) {
#pragma unroll
            for (int j = 0; j < 16; j++) { re[j] = pre[l*17 + j]; im[j] = pim[l*17 + j]; }
        }
        __syncwarp();
        if (l < 9) {
            fftN<16>(re, im, 1.f);
#pragma unroll
            for (int w = 0; w < 16; w++) { pre[w*17 + l] = re[w]; pim[w*17 + l] = im[w]; }
        }
        __syncwarp();
        // stage4: irfft over kh for w=l; write result [h][w] into re-plane
        {
            float br[9], bi[9];
#pragma unroll
            for (int k = 0; k < 9; k++) { br[k] = pre[l*17 + k]; bi[k] = pim[l*17 + k]; }
            __syncwarp();
#pragma unroll
            for (int h = 0; h < 16; h++) {
                float y = br[0] + ((h & 1) ? -br[8] : br[8]);
#pragma unroll
                for (int k = 1; k < 8; k++) {
                    const int idx = (k*h) & 15;
                    y += 2.f*(br[k]*CT16[idx] - bi[k]*ST16[idx]);
                }
                pre[h*17 + l] = y*(1.f/256.f);
            }
        }
    } else {
        // conv3x3 on t1, 2 tokens/thread, results (incl. conv bias) -> cb
        const int base = tid - 128;
#pragma unroll
        for (int r = 0; r < 2; r++) {
            const int t = base + r*128;
            const int h = t >> 4, w = t & 15;
            float acc[8];
#pragma unroll
            for (int c = 0; c < 8; c++) acc[c] = WS[640 + c];
            conv_acc<16>(acc, t1, h, w, WS + 64);
            *reinterpret_cast<float4*>(cb + t*8)     = make_float4(acc[0],acc[1],acc[2],acc[3]);
            *reinterpret_cast<float4*>(cb + t*8 + 4) = make_float4(acc[4],acc[5],acc[6],acc[7]);
        }
    }
    __syncthreads();

    // epilogue: LN2 + MLP + (conv) + LN3 + relu
    {
        const int t = tid;
        const int h = t >> 4, w = t & 15;
        float v[8], xn[8];
#pragma unroll
        for (int c = 0; c < 8; c++) v[c] = PL[c*272 + h*17 + w];
        ln8(v, WS+16, WS+24, xn);
        float acc[8];
        const float4 c0 = *reinterpret_cast<const float4*>(cb + t*8);
        const float4 c1 = *reinterpret_cast<const float4*>(cb + t*8 + 4);
        acc[0]=c0.x+WS[1872+0]; acc[1]=c0.y+WS[1872+1]; acc[2]=c0.z+WS[1872+2]; acc[3]=c0.w+WS[1872+3];
        acc[4]=c1.x+WS[1872+4]; acc[5]=c1.y+WS[1872+5]; acc[6]=c1.z+WS[1872+6]; acc[7]=c1.w+WS[1872+7];
        mlp_ln_store(xn, acc, WS, 1232, 1616, WS+32, WS+40, gout + t*8, act);
    }
    __syncthreads();
}

// ---------------- z branch: 4 batches together, H=8 ----------------
__device__ void branch_z4(const float* __restrict__ xgrp, float* __restrict__ ogrp,
                          const float* __restrict__ spec, float* __restrict__ smem,
                          int b0, int nb) {
    float* WS = smem;
    float* t1 = smem + OFF_T1;
    float* PL = smem + OFF_PL;
    const int tid = threadIdx.x;
    const int lane = tid & 31;
    const int wid  = tid >> 5;

    // LN1 for 4 batches (t = sb*64 + tt)
    {
        const int t = tid;
        const int sb = t >> 6, tt = t & 63;
        const bool act = (b0 + sb) < nb;
        float v[8] = {0,0,0,0,0,0,0,0};
        if (act) {
            const float4 a = *reinterpret_cast<const float4*>(xgrp + (size_t)sb*2560 + tt*8);
            const float4 b = *reinterpret_cast<const float4*>(xgrp + (size_t)sb*2560 + tt*8 + 4);
            v[0]=a.x; v[1]=a.y; v[2]=a.z; v[3]=a.w; v[4]=b.x; v[5]=b.y; v[6]=b.z; v[7]=b.w;
        }
        float o[8];
        ln8(v, WS+0, WS+8, o);
        *reinterpret_cast<float4*>(t1 + t*12)     = make_float4(o[0],o[1],o[2],o[3]);
        *reinterpret_cast<float4*>(t1 + t*12 + 4) = make_float4(o[4],o[5],o[6],o[7]);
        const int h = tt >> 3, w = tt & 7;
#pragma unroll
        for (int c = 0; c < 8; c++) PL[2304 + (sb*8+c)*72 + w*9 + h] = o[c];
    }
    __syncthreads();

    // spectral: 32 (batch,channel) pairs, 8 lanes each -> all 8 warps full
    {
        const int P = wid*4 + (lane >> 3);   // P = sb*8 + c
        const int c = P & 7;
        const int l = lane & 7;
        float* pre = PL + P*72;
        float* pim = PL + 2304 + P*72;
        float re[8], im[8];
        // stage1
#pragma unroll
        for (int j = 0; j < 8; j++) { re[j] = pim[j*9 + l]; im[j] = 0.f; }
        fftN<8>(re, im, -1.f);
#pragma unroll
        for (int k = 0; k < 8; k++) { pre[k*9 + l] = re[k]; pim[k*9 + l] = im[k]; }
        __syncwarp();
        // stage2 + weights
#pragma unroll
        for (int j = 0; j < 8; j++) { re[j] = pre[l*9 + j]; im[j] = pim[l*9 + j]; }
        __syncwarp();
        fftN<8>(re, im, -1.f);
#pragma unroll
        for (int kh = 0; kh < 5; kh++) {
            const float wr = __ldg(&spec[((l*5 + kh)*8 + c)*2 + 0]);
            const float wi = __ldg(&spec[((l*5 + kh)*8 + c)*2 + 1]);
            pre[kh*9 + l] = re[kh]*wr - im[kh]*wi;
            pim[kh*9 + l] = re[kh]*wi + im[kh]*wr;
        }
        __syncwarp();
        // stage3 (kh = l < 5)
        if (l < 5) {
#pragma unroll
            for (int j = 0; j < 8; j++) { re[j] = pre[l*9 + j]; im[j] = pim[l*9 + j]; }
        }
        __syncwarp();
        if (l < 5) {
            fftN<8>(re, im, 1.f);
#pragma unroll
            for (int w = 0; w < 8; w++) { pre[w*9 + l] = re[w]; pim[w*9 + l] = im[w]; }
        }
        __syncwarp();
        // stage4: irfft, result [h][w] into re-plane
        {
            float br[5], bi[5];
#pragma unroll
            for (int k = 0; k < 5; k++) { br[k] = pre[l*9 + k]; bi[k] = pim[l*9 + k]; }
            __syncwarp();
#pragma unroll
            for (int h = 0; h < 8; h++) {
                float y = br[0] + ((h & 1) ? -br[4] : br[4]);
#pragma unroll
                for (int k = 1; k < 4; k++) {
                    const int idx = (k*h*2) & 15;
                    y += 2.f*(br[k]*CT16[idx] - bi[k]*ST16[idx]);
                }
                pre[h*9 + l] = y*(1.f/64.f);
            }
        }
    }
    __syncthreads();

    // epilogue
    {
        const int t = tid;
        const int sb = t >> 6, tt = t & 63;
        const int h = tt >> 3, w = tt & 7;
        const bool act = (b0 + sb) < nb;
        float v[8], xn[8];
#pragma unroll
        for (int c = 0; c < 8; c++) v[c] = PL[(sb*8+c)*72 + h*9 + w];
        ln8(v, WS+16, WS+24, xn);
        float acc[8];
#pragma unroll
        for (int c = 0; c < 8; c++) acc[c] = WS[1224 + c] + WS[2520 + c];
        conv_acc<8>(acc, t1 + sb*64*12, h, w, WS + 648);
        mlp_ln_store(xn, acc, WS, 1880, 2264, WS+48, WS+56,
                     ogrp + (size_t)sb*2560 + tt*8, act);
    }
    __syncthreads();
}

__global__ void __launch_bounds__(256, 4)
sg_kernel(const float* __restrict__ x,
          const float* __restrict__ n1g, const float* __restrict__ n1b,
          const float* __restrict__ n2g, const float* __restrict__ n2b,
          const float* __restrict__ n3g, const float* __restrict__ n3b,
          const float* __restrict__ n4g, const float* __restrict__ n4b,
          const float* __restrict__ c1w, const float* __restrict__ c1b,
          const float* __restrict__ c2w, const float* __restrict__ c2b,
          const float* __restrict__ m1w1, const float* __restrict__ m1b1,
          const float* __restrict__ m1w2, const float* __restrict__ m1b2,
          const float* __restrict__ m2w1, const float* __restrict__ m2b1,
          const float* __restrict__ m2w2, const float* __restrict__ m2b2,
          const float* __restrict__ cw,  const float* __restrict__ cwz,
          float* __restrict__ out, int nb)
{
    __shared__ float smem[SMEM_FLOATS];
    float* WS = smem;
    const int tid = threadIdx.x;

    // ---- stage weights ----
    if (tid < 8) {
        WS[tid]      = n1g[tid]; WS[8+tid]    = n1b[tid];
        WS[16+tid]   = n2g[tid]; WS[24+tid]   = n2b[tid];
        WS[32+tid]   = n3g[tid]; WS[40+tid]   = n3b[tid];
        WS[48+tid]   = n4g[tid]; WS[56+tid]   = n4b[tid];
        WS[640+tid]  = c1b[tid]; WS[1224+tid] = c2b[tid];
        WS[1872+tid] = m1b2[tid];WS[2520+tid] = m2b2[tid];
    }
    if (tid < 32) { WS[1232 + tid*12 + 8] = m1b1[tid]; WS[1880 + tid*12 + 8] = m2b1[tid]; }
    {
        const int j = tid >> 3, c = tid & 7;
        WS[1232 + j*12 + c] = m1w1[c*32 + j];   // W1 transposed: rows [j][c], pitch 12
        WS[1880 + j*12 + c] = m2w1[c*32 + j];
        WS[1616 + tid] = m1w2[tid];             // W2 rows [j][c]
        WS[2264 + tid] = m2w2[tid];
    }
    for (int i = tid; i < 576; i += 256) {       // conv OIHW -> [tap][ci][co]
        const int co = i/72, r = i%72, ci = r/9, tap = r%9;
        WS[64  + tap*64 + ci*8 + co] = c1w[i];
        WS[648 + tap*64 + ci*8 + co] = c2w[i];
    }
    __syncthreads();

    const int g = blockIdx.x;          // one group of 4 batches per CTA
    const int b0 = g*4;
    if (b0 >= nb) return;
    const float* xb = x   + (size_t)b0*2560;
    float*       ob = out + (size_t)b0*2560;

#pragma unroll 1
    for (int q = 0; q < 4; q++) {
        const bool act = (b0 + q) < nb;
        branch_x(xb + (size_t)q*2560 + 512, ob + (size_t)q*2560 + 512, cw, smem, act);
    }
    branch_z4(xb, ob, cwz, smem, b0, nb);
}

extern "C" void kernel_launch(void* const* d_in, const int* in_sizes, int n_in,
                              void* d_out, int out_size) {
    const float* P[23];
    for (int i = 0; i < 23; i++) P[i] = (const float*)d_in[i];
    const int nb = in_sizes[0] / 2560;
    const int grid = (nb + 3) / 4;
    sg_kernel<<<grid, 256>>>(P[0], P[1], P[2], P[3], P[4], P[5], P[6], P[7], P[8],
                             P[9], P[10], P[11], P[12], P[13], P[14], P[15], P[16],
                             P[17], P[18], P[19], P[20], P[21], P[22],
                             (float*)d_out, nb);
}